// round 5
// baseline (speedup 1.0000x reference)
#include <cuda_runtime.h>
#include <cstdint>

// ---------------- problem constants ----------------
// B=16, H=W=64, C=512, NH=16, hd=32, WS=8, N=64, SS=4
// rows (window-token order) = B*nW*N = 65536

// ---------------- device scratch (no cudaMalloc allowed) ----------------
__device__ float g_q[1024 * 16 * 64 * 32];
__device__ float g_k[1024 * 16 * 64 * 32];
__device__ float g_v[1024 * 16 * 64 * 32];
__device__ float g_att[65536 * 512];
__device__ float g_bias[16 * 64 * 64];

// ---------------- helpers ----------------
__device__ __forceinline__ float to_tf32(float x) {
    float r;
    asm("cvt.rna.tf32.f32 %0, %1;" : "=f"(r) : "f"(x));
    return r;
}

#define MMA8(c, a0, a1, a2, a3, b0, b1)                                      \
    asm volatile(                                                            \
        "mma.sync.aligned.m16n8k8.row.col.f32.tf32.tf32.f32 "                \
        "{%0,%1,%2,%3}, {%4,%5,%6,%7}, {%8,%9}, {%0,%1,%2,%3};\n"            \
        : "+f"((c)[0]), "+f"((c)[1]), "+f"((c)[2]), "+f"((c)[3])             \
        : "r"(a0), "r"(a1), "r"(a2), "r"(a3), "r"(b0), "r"(b1))

// window-token row -> original image row (shift + window partition fused).
__device__ __forceinline__ int permute_row(int r) {
    int b   = r >> 12;
    int rem = r & 4095;
    int wi  = rem >> 6, n = rem & 63;
    int hs  = ((wi >> 3) << 3) | (n >> 3);
    int ws  = ((wi & 7) << 3) | (n & 7);
    int hp  = (hs + 4) & 63;
    int wp  = (ws + 4) & 63;
    return (b << 12) | (hp << 6) | wp;
}

// ---------------- K0: expand relative-position bias ----------------
__global__ void k_bias_pre(const float* __restrict__ bt, const int* __restrict__ ri) {
    int h = blockIdx.x;  // 0..15
    for (int nm = threadIdx.x; nm < 4096; nm += blockDim.x)
        g_bias[h * 4096 + nm] = bt[ri[nm] * 16 + h];
}

// ---------------- K1/K3: tiled tf32 GEMM (NT), 128x128x32, 256 thr ----------------
// Fragment layout: within each k-group of 8, elements permuted as
// perm(k) = 2*(k&3) + ((k>>2)&1) so each MMA fragment pair (k=t, k=t+4) is
// ADJACENT -> single LDS.64. Row stride = 40 floats (conflict-free LDS.64).
// blockIdx.x = COLUMN tile (L2 reuse of A row tile); blockIdx.y = row tile.
template <bool IS_QKV>
__global__ __launch_bounds__(256, 2) void k_gemm(const float* __restrict__ Aglob,
                                                 const float* __restrict__ Wglob,
                                                 const float* __restrict__ bias,
                                                 float* __restrict__ outp) {
    __shared__ float smem[2 * 128 * 40];   // 40960 B; A tile + B tile; C staging reuse
    float* As = smem;                      // 128 * 40
    float* Bs = smem + 128 * 40;           // 128 * 40

    const float* Asrc = IS_QKV ? Aglob : (const float*)g_att;

    const int Cb   = blockIdx.x * 128;     // column tile (fast axis)
    const int Rb   = blockIdx.y * 128;     // row tile
    const int tid  = threadIdx.x;
    const int lane = tid & 31, wid = tid >> 5;
    const int g = lane >> 2, t = lane & 3;
    const int wm = wid & 1, wn = wid >> 1;
    const int m0 = wm * 64, n0 = wn * 32;

    // per-thread loads: each thread owns 4 consecutive k (c*4..c*4+3) of one row
    const int lrow = tid >> 3, c = tid & 7, lc = c * 4;
    // permuted smem offset: row*40 + (c>>1)*8 + (c&1), elements at +2j
    const int off0 = lrow * 40 + ((c >> 1) << 3) + (c & 1);

    const float* aptr[4];
#pragma unroll
    for (int i = 0; i < 4; i++) {
        int row = lrow + i * 32;
        int src = IS_QKV ? permute_row(Rb + row) : (Rb + row);
        aptr[i] = Asrc + (size_t)src * 512 + lc;
    }
    const float* bbase = Wglob + (size_t)(Cb + lrow) * 512 + lc;

    float4 ra[4], rb[4];
#pragma unroll
    for (int i = 0; i < 4; i++) ra[i] = *(const float4*)(aptr[i]);
#pragma unroll
    for (int i = 0; i < 4; i++) rb[i] = *(const float4*)(bbase + (size_t)i * 32 * 512);

    float acc[4][4][4];
#pragma unroll
    for (int a = 0; a < 4; a++)
#pragma unroll
        for (int b = 0; b < 4; b++)
#pragma unroll
            for (int cc = 0; cc < 4; cc++) acc[a][b][cc] = 0.f;

#pragma unroll 1
    for (int kt = 0; kt < 16; kt++) {
        // store current registers -> smem (tf32-rounded, k-permuted: +2j stride)
#pragma unroll
        for (int i = 0; i < 4; i++) {
            float* d = As + off0 + i * 32 * 40;
            d[0] = to_tf32(ra[i].x); d[2] = to_tf32(ra[i].y);
            d[4] = to_tf32(ra[i].z); d[6] = to_tf32(ra[i].w);
        }
#pragma unroll
        for (int i = 0; i < 4; i++) {
            float* d = Bs + off0 + i * 32 * 40;
            d[0] = to_tf32(rb[i].x); d[2] = to_tf32(rb[i].y);
            d[4] = to_tf32(rb[i].z); d[6] = to_tf32(rb[i].w);
        }
        __syncthreads();

        // prefetch next K-tile while MMAs run
        if (kt < 15) {
            const int k0 = (kt + 1) * 32;
#pragma unroll
            for (int i = 0; i < 4; i++) ra[i] = *(const float4*)(aptr[i] + k0);
#pragma unroll
            for (int i = 0; i < 4; i++)
                rb[i] = *(const float4*)(bbase + (size_t)i * 32 * 512 + k0);
        }

        // fragment loads as float2 (LDS.64): index in float2 units = row*20 + ks*4 + t
        const float2* A2 = (const float2*)As;
        const float2* B2 = (const float2*)Bs;
#pragma unroll
        for (int ks = 0; ks < 4; ks++) {
            const int kf = ks * 4 + t;
            uint32_t a[4][4];
#pragma unroll
            for (int mf = 0; mf < 4; mf++) {
                float2 lo = A2[(m0 + mf * 16 + g) * 20 + kf];
                float2 hi = A2[(m0 + mf * 16 + 8 + g) * 20 + kf];
                a[mf][0] = __float_as_uint(lo.x);
                a[mf][1] = __float_as_uint(hi.x);
                a[mf][2] = __float_as_uint(lo.y);
                a[mf][3] = __float_as_uint(hi.y);
            }
#pragma unroll
            for (int nf = 0; nf < 4; nf++) {
                float2 bb = B2[(n0 + nf * 8 + g) * 20 + kf];
                uint32_t b0 = __float_as_uint(bb.x), b1 = __float_as_uint(bb.y);
#pragma unroll
                for (int mf = 0; mf < 4; mf++)
                    MMA8(acc[mf][nf], a[mf][0], a[mf][1], a[mf][2], a[mf][3], b0, b1);
            }
        }
        __syncthreads();
    }

    // epilogue: stage 128x64 halves through smem for coalesced permuted writes
    float* st = smem;  // 128*65 = 8320 floats
#pragma unroll 1
    for (int half = 0; half < 2; half++) {
        if ((wn >> 1) == half) {
            const int nbase = n0 - half * 64;
#pragma unroll
            for (int mf = 0; mf < 4; mf++)
#pragma unroll
                for (int nf = 0; nf < 4; nf++) {
                    int row = m0 + mf * 16 + g;
                    int col = nbase + nf * 8 + 2 * t;
                    st[row * 65 + col]           = acc[mf][nf][0];
                    st[row * 65 + col + 1]       = acc[mf][nf][1];
                    st[(row + 8) * 65 + col]     = acc[mf][nf][2];
                    st[(row + 8) * 65 + col + 1] = acc[mf][nf][3];
                }
        }
        __syncthreads();

        const int Co = Cb + half * 64;
        if (IS_QKV) {
            const int s = Co >> 9;  // 0=q 1=k 2=v (uniform: Co is 64-aligned)
            float* buf  = (s == 0) ? g_q : (s == 1) ? g_k : g_v;
#pragma unroll
            for (int i = 0; i < 32; i++) {
                int idx = tid + i * 256;
                int m = idx >> 6, j = idx & 63;
                int r = Rb + m, o = Co + j;
                int hh = (o >> 5) & 15, d = o & 31;
                int wnd = r >> 6, n = r & 63;
                buf[((size_t)((wnd * 16 + hh) * 64 + n)) * 32 + d] = st[m * 65 + j] + bias[o];
            }
        } else {
#pragma unroll
            for (int i = 0; i < 32; i++) {
                int idx = tid + i * 256;
                int m = idx >> 6, j = idx & 63;
                int r = Rb + m, o = Co + j;
                int dst = permute_row(r);
                outp[(size_t)dst * 512 + o] = st[m * 65 + j] + bias[o];
            }
        }
        __syncthreads();
    }
}

// ---------------- K2: attention, one block per (window, head) ----------------
__global__ __launch_bounds__(128) void k_attn() {
    __shared__ float qs[64 * 36];
    __shared__ float kt_s[64 * 36];
    __shared__ float vs[64 * 36];
    __shared__ float ps[64 * 68];
    __shared__ int sid[64];

    const int w   = blockIdx.x;  // 0..1023
    const int h   = blockIdx.y;  // 0..15
    const int tid = threadIdx.x;
    const int lane = tid & 31, wid = tid >> 5;
    const int g = lane >> 2, t = lane & 3;

    const size_t base = (size_t)(w * 16 + h) * 2048;  // 64*32
    const float scale = 0.17677669529663687f;         // 32^-0.5

#pragma unroll
    for (int i = 0; i < 4; i++) {
        int ch  = tid + i * 128;  // 512 chunks of 16B
        int row = ch >> 3, c = ch & 7;
        int go = row * 32 + c * 4;
        int so = row * 36 + c * 4;
        float4 q4 = *(const float4*)(g_q + base + go);
        qs[so] = to_tf32(q4.x * scale); qs[so + 1] = to_tf32(q4.y * scale);
        qs[so + 2] = to_tf32(q4.z * scale); qs[so + 3] = to_tf32(q4.w * scale);
        float4 k4 = *(const float4*)(g_k + base + go);
        kt_s[so] = to_tf32(k4.x); kt_s[so + 1] = to_tf32(k4.y);
        kt_s[so + 2] = to_tf32(k4.z); kt_s[so + 3] = to_tf32(k4.w);
        float4 v4 = *(const float4*)(g_v + base + go);
        vs[so] = to_tf32(v4.x); vs[so + 1] = to_tf32(v4.y);
        vs[so + 2] = to_tf32(v4.z); vs[so + 3] = to_tf32(v4.w);
    }
    if (tid < 64) {
        int wIdx = w & 63;
        int hs = ((wIdx >> 3) << 3) | (tid >> 3);
        int ws = ((wIdx & 7) << 3) | (tid & 7);
        int rh = (hs < 56) ? 0 : (hs < 60 ? 1 : 2);
        int rw = (ws < 56) ? 0 : (ws < 60 ? 1 : 2);
        sid[tid] = rh * 3 + rw;
    }
    __syncthreads();

    // S = q @ k^T  (warp owns 16 rows)
    const int m0 = wid * 16;
    float acc[8][4];
#pragma unroll
    for (int a = 0; a < 8; a++)
#pragma unroll
        for (int b = 0; b < 4; b++) acc[a][b] = 0.f;

    const uint32_t* Q = (const uint32_t*)qs;
    const uint32_t* K = (const uint32_t*)kt_s;
#pragma unroll
    for (int ks = 0; ks < 4; ks++) {
        const int kk = ks * 8 + t;
        int ab = (m0 + g) * 36 + kk;
        uint32_t a0 = Q[ab], a1 = Q[ab + 8 * 36], a2 = Q[ab + 4], a3 = Q[ab + 8 * 36 + 4];
#pragma unroll
        for (int nf = 0; nf < 8; nf++) {
            int nb = (nf * 8 + g) * 36 + kk;
            MMA8(acc[nf], a0, a1, a2, a3, K[nb], K[nb + 4]);
        }
    }

    // + rel-pos bias + shift mask, then softmax (rows split over lane quads)
    const float* bh = g_bias + h * 4096;
    const int r0 = m0 + g, r1 = r0 + 8;
    const int id0 = sid[r0], id1 = sid[r1];
    float mx0 = -1e30f, mx1 = -1e30f;
#pragma unroll
    for (int nf = 0; nf < 8; nf++) {
        int c0 = nf * 8 + 2 * t;
        int ic0 = sid[c0], ic1 = sid[c0 + 1];
        acc[nf][0] += bh[r0 * 64 + c0]     + (id0 != ic0 ? -100.f : 0.f);
        acc[nf][1] += bh[r0 * 64 + c0 + 1] + (id0 != ic1 ? -100.f : 0.f);
        acc[nf][2] += bh[r1 * 64 + c0]     + (id1 != ic0 ? -100.f : 0.f);
        acc[nf][3] += bh[r1 * 64 + c0 + 1] + (id1 != ic1 ? -100.f : 0.f);
        mx0 = fmaxf(mx0, fmaxf(acc[nf][0], acc[nf][1]));
        mx1 = fmaxf(mx1, fmaxf(acc[nf][2], acc[nf][3]));
    }
    mx0 = fmaxf(mx0, __shfl_xor_sync(0xffffffffu, mx0, 1));
    mx0 = fmaxf(mx0, __shfl_xor_sync(0xffffffffu, mx0, 2));
    mx1 = fmaxf(mx1, __shfl_xor_sync(0xffffffffu, mx1, 1));
    mx1 = fmaxf(mx1, __shfl_xor_sync(0xffffffffu, mx1, 2));
    float s0 = 0.f, s1 = 0.f;
#pragma unroll
    for (int nf = 0; nf < 8; nf++) {
        acc[nf][0] = __expf(acc[nf][0] - mx0); s0 += acc[nf][0];
        acc[nf][1] = __expf(acc[nf][1] - mx0); s0 += acc[nf][1];
        acc[nf][2] = __expf(acc[nf][2] - mx1); s1 += acc[nf][2];
        acc[nf][3] = __expf(acc[nf][3] - mx1); s1 += acc[nf][3];
    }
    s0 += __shfl_xor_sync(0xffffffffu, s0, 1);
    s0 += __shfl_xor_sync(0xffffffffu, s0, 2);
    s1 += __shfl_xor_sync(0xffffffffu, s1, 1);
    s1 += __shfl_xor_sync(0xffffffffu, s1, 2);
    const float inv0 = 1.f / s0, inv1 = 1.f / s1;
#pragma unroll
    for (int nf = 0; nf < 8; nf++) {
        int c0 = nf * 8 + 2 * t;
        ps[r0 * 68 + c0]     = to_tf32(acc[nf][0] * inv0);
        ps[r0 * 68 + c0 + 1] = to_tf32(acc[nf][1] * inv0);
        ps[r1 * 68 + c0]     = to_tf32(acc[nf][2] * inv1);
        ps[r1 * 68 + c0 + 1] = to_tf32(acc[nf][3] * inv1);
    }
    __syncthreads();

    // O = P @ V
    float acc2[4][4];
#pragma unroll
    for (int a = 0; a < 4; a++)
#pragma unroll
        for (int b = 0; b < 4; b++) acc2[a][b] = 0.f;
    const uint32_t* P = (const uint32_t*)ps;
    const uint32_t* V = (const uint32_t*)vs;
#pragma unroll
    for (int ks = 0; ks < 8; ks++) {
        const int kk = ks * 8 + t;
        int ab = (m0 + g) * 68 + kk;
        uint32_t a0 = P[ab], a1 = P[ab + 8 * 68], a2 = P[ab + 4], a3 = P[ab + 8 * 68 + 4];
#pragma unroll
        for (int nf = 0; nf < 4; nf++) {
            int nn = nf * 8 + g;
            MMA8(acc2[nf], a0, a1, a2, a3, V[kk * 36 + nn], V[(kk + 4) * 36 + nn]);
        }
    }

    // stage O (reuse qs) then coalesced store to g_att[(w*64+n)*512 + h*32 + d]
    float* ost = qs;
#pragma unroll
    for (int nf = 0; nf < 4; nf++) {
        int c0 = nf * 8 + 2 * t;
        ost[r0 * 36 + c0]     = acc2[nf][0];
        ost[r0 * 36 + c0 + 1] = acc2[nf][1];
        ost[r1 * 36 + c0]     = acc2[nf][2];
        ost[r1 * 36 + c0 + 1] = acc2[nf][3];
    }
    __syncthreads();
    const size_t ob = (size_t)(w * 64) * 512 + h * 32;
#pragma unroll
    for (int i = 0; i < 16; i++) {
        int idx = tid + i * 128;
        int row = idx >> 5, d = idx & 31;
        g_att[ob + (size_t)row * 512 + d] = ost[row * 36 + d];
    }
}

// ---------------- launch ----------------
extern "C" void kernel_launch(void* const* d_in, const int* in_sizes, int n_in,
                              void* d_out, int out_size) {
    // Bind inputs by unique element count — order-proof against metadata layout.
    const float* x  = nullptr;  // 33554432
    const float* qw = nullptr;  // 786432
    const float* qb = nullptr;  // 1536
    const float* pw = nullptr;  // 262144
    const float* pb = nullptr;  // 512
    const float* bt = nullptr;  // 3600
    const int*   ri = nullptr;  // 4096
    for (int i = 0; i < n_in; i++) {
        switch (in_sizes[i]) {
            case 33554432: x  = (const float*)d_in[i]; break;
            case 786432:   qw = (const float*)d_in[i]; break;
            case 1536:     qb = (const float*)d_in[i]; break;
            case 262144:   pw = (const float*)d_in[i]; break;
            case 512:      pb = (const float*)d_in[i]; break;
            case 3600:     bt = (const float*)d_in[i]; break;
            case 4096:     ri = (const int*)d_in[i];   break;
            default: break;  // H, W scalars — unused (statically known)
        }
    }
    float* out = (float*)d_out;

    k_bias_pre<<<16, 256>>>(bt, ri);
    // blockIdx.x = column tile (12 for QKV, 4 for proj), blockIdx.y = row tile
    k_gemm<true><<<dim3(12, 512), 256>>>(x, qw, qb, nullptr);
    k_attn<<<dim3(1024, 16), 128>>>();
    k_gemm<false><<<dim3(4, 512), 256>>>(nullptr, pw, pb, out);
}

// round 6
// speedup vs baseline: 1.4768x; 1.4768x over previous
#include <cuda_runtime.h>
#include <cstdint>

// ---------------- problem constants ----------------
// B=16, H=W=64, C=512, NH=16, hd=32, WS=8, N=64, SS=4
// rows (window-token order) = B*nW*N = 65536

// ---------------- device scratch (no cudaMalloc allowed) ----------------
__device__ float g_q[1024 * 16 * 64 * 32];
__device__ float g_k[1024 * 16 * 64 * 32];
__device__ float g_v[1024 * 16 * 64 * 32];
__device__ float g_att[65536 * 512];
__device__ float g_bias[16 * 64 * 64];

// ---------------- helpers ----------------
__device__ __forceinline__ float to_tf32(float x) {
    float r;
    asm("cvt.rna.tf32.f32 %0, %1;" : "=f"(r) : "f"(x));
    return r;
}

#define MMA8(c, a0, a1, a2, a3, b0, b1)                                      \
    asm volatile(                                                            \
        "mma.sync.aligned.m16n8k8.row.col.f32.tf32.tf32.f32 "                \
        "{%0,%1,%2,%3}, {%4,%5,%6,%7}, {%8,%9}, {%0,%1,%2,%3};\n"            \
        : "+f"((c)[0]), "+f"((c)[1]), "+f"((c)[2]), "+f"((c)[3])             \
        : "r"(a0), "r"(a1), "r"(a2), "r"(a3), "r"(b0), "r"(b1))

// window-token row -> original image row (shift + window partition fused).
__device__ __forceinline__ int permute_row(int r) {
    int b   = r >> 12;
    int rem = r & 4095;
    int wi  = rem >> 6, n = rem & 63;
    int hs  = ((wi >> 3) << 3) | (n >> 3);
    int ws  = ((wi & 7) << 3) | (n & 7);
    int hp  = (hs + 4) & 63;
    int wp  = (ws + 4) & 63;
    return (b << 12) | (hp << 6) | wp;
}

// ---------------- K0: expand relative-position bias ----------------
__global__ void k_bias_pre(const float* __restrict__ bt, const int* __restrict__ ri) {
    int h = blockIdx.x;  // 0..15
    for (int nm = threadIdx.x; nm < 4096; nm += blockDim.x)
        g_bias[h * 4096 + nm] = bt[ri[nm] * 16 + h];
}

// ---------------- K1/K3: tiled tf32 GEMM (NT), 256x128x32, 256 thr ----------------
// 8 warps, each with a 64x64 warp tile (4 m-splits x 2 n-splits):
// per k=8 step: 16 A-LDS + 16 B-LDS for 32 MMAs (ratio 1.0 vs 1.5 at 64x32).
// R4-style smem: row stride 36 floats, consecutive tf32 stores (STS.128),
// scalar LDS.32 fragment loads (conflict-free).
// blockIdx.x = COLUMN tile (L2 reuse of A row tile); blockIdx.y = row tile.
template <bool IS_QKV>
__global__ __launch_bounds__(256, 1) void k_gemm(const float* __restrict__ Aglob,
                                                 const float* __restrict__ Wglob,
                                                 const float* __restrict__ bias,
                                                 float* __restrict__ outp) {
    extern __shared__ float smem[];        // 384*36 floats = 55296 B (dynamic)
    float* As = smem;                      // 256 * 36
    float* Bs = smem + 256 * 36;           // 128 * 36

    const float* Asrc = IS_QKV ? Aglob : (const float*)g_att;

    const int Cb   = blockIdx.x * 128;     // column tile (fast axis)
    const int Rb   = blockIdx.y * 256;     // row tile
    const int tid  = threadIdx.x;
    const int lane = tid & 31, wid = tid >> 5;
    const int g = lane >> 2, t = lane & 3;
    const int wm = wid & 3, wn = wid >> 2;
    const int m0 = wm * 64, n0 = wn * 64;

    // per-thread loads: A 2048 16B chunks (8/thr), B 1024 (4/thr)
    const int lrow = tid >> 3, lc = (tid & 7) * 4;
    const int off0 = lrow * 36 + lc;       // smem offset chunk 0; +32*36 per chunk

    // A row offsets (permuted rows -> precompute global element offsets)
    int aoffg[8];
#pragma unroll
    for (int i = 0; i < 8; i++) {
        int row = lrow + i * 32;
        int src = IS_QKV ? permute_row(Rb + row) : (Rb + row);
        aoffg[i] = src * 512 + lc;
    }
    const float* bbase = Wglob + (size_t)(Cb + lrow) * 512 + lc;

    float4 ra[8], rb[4];
#pragma unroll
    for (int i = 0; i < 8; i++) ra[i] = *(const float4*)(Asrc + (size_t)aoffg[i]);
#pragma unroll
    for (int i = 0; i < 4; i++) rb[i] = *(const float4*)(bbase + (size_t)i * 32 * 512);

    float acc[4][8][4];
#pragma unroll
    for (int a = 0; a < 4; a++)
#pragma unroll
        for (int b = 0; b < 8; b++)
#pragma unroll
            for (int cc = 0; cc < 4; cc++) acc[a][b][cc] = 0.f;

#pragma unroll 1
    for (int kt = 0; kt < 16; kt++) {
        // store current registers -> smem (tf32-rounded, consecutive -> STS.128)
#pragma unroll
        for (int i = 0; i < 8; i++) {
            float* d = As + off0 + i * 32 * 36;
            d[0] = to_tf32(ra[i].x); d[1] = to_tf32(ra[i].y);
            d[2] = to_tf32(ra[i].z); d[3] = to_tf32(ra[i].w);
        }
#pragma unroll
        for (int i = 0; i < 4; i++) {
            float* d = Bs + off0 + i * 32 * 36;
            d[0] = to_tf32(rb[i].x); d[1] = to_tf32(rb[i].y);
            d[2] = to_tf32(rb[i].z); d[3] = to_tf32(rb[i].w);
        }
        __syncthreads();

        // prefetch next K-tile while MMAs run
        if (kt < 15) {
            const int k0 = (kt + 1) * 32;
#pragma unroll
            for (int i = 0; i < 8; i++)
                ra[i] = *(const float4*)(Asrc + (size_t)aoffg[i] + k0);
#pragma unroll
            for (int i = 0; i < 4; i++)
                rb[i] = *(const float4*)(bbase + (size_t)i * 32 * 512 + k0);
        }

        const uint32_t* A = (const uint32_t*)As;
        const uint32_t* B = (const uint32_t*)Bs;
#pragma unroll
        for (int ks = 0; ks < 4; ks++) {
            const int kk = ks * 8 + t;
            uint32_t a[4][4];
#pragma unroll
            for (int mf = 0; mf < 4; mf++) {
                int base = (m0 + mf * 16 + g) * 36 + kk;
                a[mf][0] = A[base];
                a[mf][1] = A[base + 8 * 36];
                a[mf][2] = A[base + 4];
                a[mf][3] = A[base + 8 * 36 + 4];
            }
#pragma unroll
            for (int nf = 0; nf < 8; nf++) {
                int nb      = (n0 + nf * 8 + g) * 36 + kk;
                uint32_t b0 = B[nb], b1 = B[nb + 4];
#pragma unroll
                for (int mf = 0; mf < 4; mf++)
                    MMA8(acc[mf][nf], a[mf][0], a[mf][1], a[mf][2], a[mf][3], b0, b1);
            }
        }
        __syncthreads();
    }

    // epilogue: stage four 128x64 quarters through smem for coalesced writes
    float* st = smem;  // 128*65 = 8320 floats (fits)
#pragma unroll 1
    for (int q = 0; q < 4; q++) {
        const int rh = q >> 1, ch = q & 1;
        if ((wm >> 1) == rh && wn == ch) {
            const int rbase = (wm & 1) * 64;
#pragma unroll
            for (int mf = 0; mf < 4; mf++)
#pragma unroll
                for (int nf = 0; nf < 8; nf++) {
                    int row = rbase + mf * 16 + g;
                    int col = nf * 8 + 2 * t;
                    st[row * 65 + col]           = acc[mf][nf][0];
                    st[row * 65 + col + 1]       = acc[mf][nf][1];
                    st[(row + 8) * 65 + col]     = acc[mf][nf][2];
                    st[(row + 8) * 65 + col + 1] = acc[mf][nf][3];
                }
        }
        __syncthreads();

        const int Ro = Rb + rh * 128;
        const int Co = Cb + ch * 64;
        if (IS_QKV) {
            const int s = Co >> 9;  // 0=q 1=k 2=v (uniform: Co is 64-aligned)
            float* buf  = (s == 0) ? g_q : (s == 1) ? g_k : g_v;
#pragma unroll
            for (int i = 0; i < 32; i++) {
                int idx = tid + i * 256;
                int m = idx >> 6, j = idx & 63;
                int r = Ro + m, o = Co + j;
                int hh = (o >> 5) & 15, d = o & 31;
                int wnd = r >> 6, n = r & 63;
                buf[((size_t)((wnd * 16 + hh) * 64 + n)) * 32 + d] = st[m * 65 + j] + bias[o];
            }
        } else {
#pragma unroll
            for (int i = 0; i < 32; i++) {
                int idx = tid + i * 256;
                int m = idx >> 6, j = idx & 63;
                int r = Ro + m, o = Co + j;
                int dst = permute_row(r);
                outp[(size_t)dst * 512 + o] = st[m * 65 + j] + bias[o];
            }
        }
        __syncthreads();
    }
}

// ---------------- K2: attention, one block per (window, head) ----------------
__global__ __launch_bounds__(128) void k_attn() {
    __shared__ float qs[64 * 36];
    __shared__ float kt_s[64 * 36];
    __shared__ float vs[64 * 36];
    __shared__ float ps[64 * 68];
    __shared__ int sid[64];

    const int w   = blockIdx.x;  // 0..1023
    const int h   = blockIdx.y;  // 0..15
    const int tid = threadIdx.x;
    const int lane = tid & 31, wid = tid >> 5;
    const int g = lane >> 2, t = lane & 3;

    const size_t base = (size_t)(w * 16 + h) * 2048;  // 64*32
    const float scale = 0.17677669529663687f;         // 32^-0.5

#pragma unroll
    for (int i = 0; i < 4; i++) {
        int ch  = tid + i * 128;  // 512 chunks of 16B
        int row = ch >> 3, c = ch & 7;
        int go = row * 32 + c * 4;
        int so = row * 36 + c * 4;
        float4 q4 = *(const float4*)(g_q + base + go);
        qs[so] = to_tf32(q4.x * scale); qs[so + 1] = to_tf32(q4.y * scale);
        qs[so + 2] = to_tf32(q4.z * scale); qs[so + 3] = to_tf32(q4.w * scale);
        float4 k4 = *(const float4*)(g_k + base + go);
        kt_s[so] = to_tf32(k4.x); kt_s[so + 1] = to_tf32(k4.y);
        kt_s[so + 2] = to_tf32(k4.z); kt_s[so + 3] = to_tf32(k4.w);
        float4 v4 = *(const float4*)(g_v + base + go);
        vs[so] = to_tf32(v4.x); vs[so + 1] = to_tf32(v4.y);
        vs[so + 2] = to_tf32(v4.z); vs[so + 3] = to_tf32(v4.w);
    }
    if (tid < 64) {
        int wIdx = w & 63;
        int hs = ((wIdx >> 3) << 3) | (tid >> 3);
        int ws = ((wIdx & 7) << 3) | (tid & 7);
        int rh = (hs < 56) ? 0 : (hs < 60 ? 1 : 2);
        int rw = (ws < 56) ? 0 : (ws < 60 ? 1 : 2);
        sid[tid] = rh * 3 + rw;
    }
    __syncthreads();

    // S = q @ k^T  (warp owns 16 rows)
    const int m0 = wid * 16;
    float acc[8][4];
#pragma unroll
    for (int a = 0; a < 8; a++)
#pragma unroll
        for (int b = 0; b < 4; b++) acc[a][b] = 0.f;

    const uint32_t* Q = (const uint32_t*)qs;
    const uint32_t* K = (const uint32_t*)kt_s;
#pragma unroll
    for (int ks = 0; ks < 4; ks++) {
        const int kk = ks * 8 + t;
        int ab = (m0 + g) * 36 + kk;
        uint32_t a0 = Q[ab], a1 = Q[ab + 8 * 36], a2 = Q[ab + 4], a3 = Q[ab + 8 * 36 + 4];
#pragma unroll
        for (int nf = 0; nf < 8; nf++) {
            int nb = (nf * 8 + g) * 36 + kk;
            MMA8(acc[nf], a0, a1, a2, a3, K[nb], K[nb + 4]);
        }
    }

    // + rel-pos bias + shift mask, then softmax (rows split over lane quads)
    const float* bh = g_bias + h * 4096;
    const int r0 = m0 + g, r1 = r0 + 8;
    const int id0 = sid[r0], id1 = sid[r1];
    float mx0 = -1e30f, mx1 = -1e30f;
#pragma unroll
    for (int nf = 0; nf < 8; nf++) {
        int c0 = nf * 8 + 2 * t;
        int ic0 = sid[c0], ic1 = sid[c0 + 1];
        acc[nf][0] += bh[r0 * 64 + c0]     + (id0 != ic0 ? -100.f : 0.f);
        acc[nf][1] += bh[r0 * 64 + c0 + 1] + (id0 != ic1 ? -100.f : 0.f);
        acc[nf][2] += bh[r1 * 64 + c0]     + (id1 != ic0 ? -100.f : 0.f);
        acc[nf][3] += bh[r1 * 64 + c0 + 1] + (id1 != ic1 ? -100.f : 0.f);
        mx0 = fmaxf(mx0, fmaxf(acc[nf][0], acc[nf][1]));
        mx1 = fmaxf(mx1, fmaxf(acc[nf][2], acc[nf][3]));
    }
    mx0 = fmaxf(mx0, __shfl_xor_sync(0xffffffffu, mx0, 1));
    mx0 = fmaxf(mx0, __shfl_xor_sync(0xffffffffu, mx0, 2));
    mx1 = fmaxf(mx1, __shfl_xor_sync(0xffffffffu, mx1, 1));
    mx1 = fmaxf(mx1, __shfl_xor_sync(0xffffffffu, mx1, 2));
    float s0 = 0.f, s1 = 0.f;
#pragma unroll
    for (int nf = 0; nf < 8; nf++) {
        acc[nf][0] = __expf(acc[nf][0] - mx0); s0 += acc[nf][0];
        acc[nf][1] = __expf(acc[nf][1] - mx0); s0 += acc[nf][1];
        acc[nf][2] = __expf(acc[nf][2] - mx1); s1 += acc[nf][2];
        acc[nf][3] = __expf(acc[nf][3] - mx1); s1 += acc[nf][3];
    }
    s0 += __shfl_xor_sync(0xffffffffu, s0, 1);
    s0 += __shfl_xor_sync(0xffffffffu, s0, 2);
    s1 += __shfl_xor_sync(0xffffffffu, s1, 1);
    s1 += __shfl_xor_sync(0xffffffffu, s1, 2);
    const float inv0 = 1.f / s0, inv1 = 1.f / s1;
#pragma unroll
    for (int nf = 0; nf < 8; nf++) {
        int c0 = nf * 8 + 2 * t;
        ps[r0 * 68 + c0]     = to_tf32(acc[nf][0] * inv0);
        ps[r0 * 68 + c0 + 1] = to_tf32(acc[nf][1] * inv0);
        ps[r1 * 68 + c0]     = to_tf32(acc[nf][2] * inv1);
        ps[r1 * 68 + c0 + 1] = to_tf32(acc[nf][3] * inv1);
    }
    __syncthreads();

    // O = P @ V
    float acc2[4][4];
#pragma unroll
    for (int a = 0; a < 4; a++)
#pragma unroll
        for (int b = 0; b < 4; b++) acc2[a][b] = 0.f;
    const uint32_t* P = (const uint32_t*)ps;
    const uint32_t* V = (const uint32_t*)vs;
#pragma unroll
    for (int ks = 0; ks < 8; ks++) {
        const int kk = ks * 8 + t;
        int ab = (m0 + g) * 68 + kk;
        uint32_t a0 = P[ab], a1 = P[ab + 8 * 68], a2 = P[ab + 4], a3 = P[ab + 8 * 68 + 4];
#pragma unroll
        for (int nf = 0; nf < 4; nf++) {
            int nn = nf * 8 + g;
            MMA8(acc2[nf], a0, a1, a2, a3, V[kk * 36 + nn], V[(kk + 4) * 36 + nn]);
        }
    }

    // stage O (reuse qs) then coalesced store to g_att[(w*64+n)*512 + h*32 + d]
    float* ost = qs;
#pragma unroll
    for (int nf = 0; nf < 4; nf++) {
        int c0 = nf * 8 + 2 * t;
        ost[r0 * 36 + c0]     = acc2[nf][0];
        ost[r0 * 36 + c0 + 1] = acc2[nf][1];
        ost[r1 * 36 + c0]     = acc2[nf][2];
        ost[r1 * 36 + c0 + 1] = acc2[nf][3];
    }
    __syncthreads();
    const size_t ob = (size_t)(w * 64) * 512 + h * 32;
#pragma unroll
    for (int i = 0; i < 16; i++) {
        int idx = tid + i * 128;
        int row = idx >> 5, d = idx & 31;
        g_att[ob + (size_t)row * 512 + d] = ost[row * 36 + d];
    }
}

// ---------------- launch ----------------
static constexpr int SMEM_GEMM_BYTES = 384 * 36 * 4;  // 55296

extern "C" void kernel_launch(void* const* d_in, const int* in_sizes, int n_in,
                              void* d_out, int out_size) {
    // Bind inputs by unique element count — order-proof against metadata layout.
    const float* x  = nullptr;  // 33554432
    const float* qw = nullptr;  // 786432
    const float* qb = nullptr;  // 1536
    const float* pw = nullptr;  // 262144
    const float* pb = nullptr;  // 512
    const float* bt = nullptr;  // 3600
    const int*   ri = nullptr;  // 4096
    for (int i = 0; i < n_in; i++) {
        switch (in_sizes[i]) {
            case 33554432: x  = (const float*)d_in[i]; break;
            case 786432:   qw = (const float*)d_in[i]; break;
            case 1536:     qb = (const float*)d_in[i]; break;
            case 262144:   pw = (const float*)d_in[i]; break;
            case 512:      pb = (const float*)d_in[i]; break;
            case 3600:     bt = (const float*)d_in[i]; break;
            case 4096:     ri = (const int*)d_in[i];   break;
            default: break;  // H, W scalars — unused (statically known)
        }
    }
    float* out = (float*)d_out;

    cudaFuncSetAttribute(k_gemm<true>, cudaFuncAttributeMaxDynamicSharedMemorySize,
                         SMEM_GEMM_BYTES);
    cudaFuncSetAttribute(k_gemm<false>, cudaFuncAttributeMaxDynamicSharedMemorySize,
                         SMEM_GEMM_BYTES);

    k_bias_pre<<<16, 256>>>(bt, ri);
    // blockIdx.x = column tile (12 for QKV, 4 for proj), blockIdx.y = row tile
    k_gemm<true><<<dim3(12, 256), 256, SMEM_GEMM_BYTES>>>(x, qw, qb, nullptr);
    k_attn<<<dim3(1024, 16), 128>>>();
    k_gemm<false><<<dim3(4, 256), 256, SMEM_GEMM_BYTES>>>(nullptr, pw, pb, out);
}